// round 5
// baseline (speedup 1.0000x reference)
#include <cuda_runtime.h>

#define N_USERS 100000
#define M_ITEMS 50000
#define NTOT    150000
#define EMBED   64
#define BATCH   8192
#define NNZ     2400000
#define SCAN_T  1024

// Static device scratch (no allocation allowed).
__device__ float g_A[(size_t)NTOT * EMBED];   // ping
__device__ float g_B[(size_t)NTOT * EMBED];   // pong
__device__ float g_S[(size_t)NTOT * EMBED];   // running sum
__device__ int   g_cnt[NTOT + 1];
__device__ int   g_rs[NTOT + 1];              // CSR row starts
__device__ int   g_cur[NTOT];                 // scatter cursors
__device__ int2  g_edge[NNZ];                 // packed (dst, val-bits), grouped by src

__device__ __forceinline__ float* pickAB(int sel) { return sel ? g_B : g_A; }

static const size_t N4 = (size_t)NTOT * EMBED / 4;

// A = S = concat(embed_user_0, embed_item_0); zero g_cnt and the reg_loss slot.
__global__ void k_init(const float* __restrict__ eu, const float* __restrict__ ei,
                       float* __restrict__ out) {
    size_t i = (size_t)blockIdx.x * blockDim.x + threadIdx.x;
    const size_t total = (size_t)NTOT * EMBED / 4;
    if (i >= total) return;
    const size_t userQ = (size_t)N_USERS * EMBED / 4;
    float4 v;
    if (i < userQ) v = reinterpret_cast<const float4*>(eu)[i];
    else           v = reinterpret_cast<const float4*>(ei)[i - userQ];
    reinterpret_cast<float4*>(g_A)[i] = v;
    reinterpret_cast<float4*>(g_S)[i] = v;
    if (i <= NTOT) g_cnt[i] = 0;
    if (i == 0) out[2 * BATCH] = 0.0f;
}

// Histogram edge sources.
__global__ void k_hist(const int* __restrict__ src) {
    unsigned int i = blockIdx.x * blockDim.x + threadIdx.x;
    if (i < NNZ) atomicAdd(&g_cnt[src[i]], 1);
}

// Single-block exclusive scan of g_cnt -> g_rs (and g_cur copy).
__global__ void k_scan() {
    __shared__ int ssum[SCAN_T];
    int t = threadIdx.x;
    const int chunk = (NTOT + SCAN_T - 1) / SCAN_T;
    int beg = t * chunk;
    int end = beg + chunk; if (end > NTOT) end = NTOT;
    int s = 0;
    for (int i = beg; i < end; i++) s += g_cnt[i];
    ssum[t] = s;
    __syncthreads();
    for (int o = 1; o < SCAN_T; o <<= 1) {
        int v = (t >= o) ? ssum[t - o] : 0;
        __syncthreads();
        if (t >= o) ssum[t] += v;
        __syncthreads();
    }
    int run = (t == 0) ? 0 : ssum[t - 1];
    for (int i = beg; i < end; i++) {
        g_rs[i] = run; g_cur[i] = run;
        run += g_cnt[i];
    }
    if (t == SCAN_T - 1) g_rs[NTOT] = run;
}

// Bucket edges by src into packed (dst, val) records.
__global__ void k_reorder(const int* __restrict__ src, const int* __restrict__ dst,
                          const float* __restrict__ vals) {
    unsigned int i = blockIdx.x * blockDim.x + threadIdx.x;
    if (i >= NNZ) return;
    int s = src[i];
    int pos = atomicAdd(&g_cur[s], 1);
    g_edge[pos] = make_int2(dst[i], __float_as_int(vals[i]));
}

// One warp per node, MLP-8 pipelined gather:
//   - lane l batch-loads edge record beg+l (one coalesced 256B load per 32 edges)
//   - rows gathered in chunks of 8 independent loads, then 8 FMAs
// Fused S += result. last=1: skip writing the ping-pong output.
__global__ void k_gather(int inSel, int last) {
    unsigned int gw = (blockIdx.x * blockDim.x + threadIdx.x) >> 5;
    if (gw >= NTOT) return;
    unsigned int lane = threadIdx.x & 31u;
    const float2* __restrict__ in = reinterpret_cast<const float2*>(pickAB(inSel));
    int beg = g_rs[gw];
    int end = g_rs[gw + 1];
    float ax = 0.0f, ay = 0.0f;
    for (int base = beg; base < end; base += 32) {
        int n = end - base; if (n > 32) n = 32;
        int2 ed = make_int2(0, 0);                       // pad: row 0, weight 0
        if (base + (int)lane < end) ed = __ldg(&g_edge[base + lane]);
        for (int k = 0; k < n; k += 8) {
            float2 x[8];
            float  v[8];
            #pragma unroll
            for (int j = 0; j < 8; j++) {
                int idx = k + j;
                int d  = __shfl_sync(0xffffffffu, ed.x, idx & 31);
                int vb = __shfl_sync(0xffffffffu, ed.y, idx & 31);
                v[j] = (idx < n) ? __int_as_float(vb) : 0.0f;   // pad lanes: ed=(0,0) -> safe
                x[j] = in[(size_t)d * (EMBED / 2) + lane];      // 8 loads in flight
            }
            #pragma unroll
            for (int j = 0; j < 8; j++) {
                ax = fmaf(v[j], x[j].x, ax);
                ay = fmaf(v[j], x[j].y, ay);
            }
        }
    }
    size_t idx = (size_t)gw * (EMBED / 2) + lane;
    if (!last) reinterpret_cast<float2*>(pickAB(inSel ^ 1))[idx] = make_float2(ax, ay);
    float2 s = reinterpret_cast<float2*>(g_S)[idx];
    reinterpret_cast<float2*>(g_S)[idx] = make_float2(s.x + ax, s.y + ay);
}

// Predictions: light_out = S/4; pred = dot(light_out[u], light_out[item]).
__global__ void k_pred(const int* __restrict__ user, const int* __restrict__ item_i,
                       const int* __restrict__ item_j, float* __restrict__ out) {
    unsigned int gw = (blockIdx.x * blockDim.x + threadIdx.x) >> 5;
    unsigned int lane = threadIdx.x & 31u;
    if (gw >= BATCH) return;
    int u  = user[gw];
    int ii = item_i[gw] + N_USERS;
    int jj = item_j[gw] + N_USERS;
    float2 ue = reinterpret_cast<const float2*>(g_S + (size_t)u  * EMBED)[lane];
    float2 ie = reinterpret_cast<const float2*>(g_S + (size_t)ii * EMBED)[lane];
    float2 je = reinterpret_cast<const float2*>(g_S + (size_t)jj * EMBED)[lane];
    float di = ue.x * ie.x + ue.y * ie.y;
    float dj = ue.x * je.x + ue.y * je.y;
    #pragma unroll
    for (int o = 16; o; o >>= 1) {
        di += __shfl_xor_sync(0xffffffffu, di, o);
        dj += __shfl_xor_sync(0xffffffffu, dj, o);
    }
    if (lane == 0) {
        out[gw]         = di * 0.0625f;   // (1/4)*(1/4)
        out[BATCH + gw] = dj * 0.0625f;
    }
}

// reg_loss = 0.5 * (sum u0^2 + sum i0^2 + sum j0^2) / BATCH
__global__ void k_reg(const int* __restrict__ user, const int* __restrict__ item_i,
                      const int* __restrict__ item_j,
                      const float* __restrict__ eu, const float* __restrict__ ei,
                      float* __restrict__ out) {
    unsigned int gw = (blockIdx.x * blockDim.x + threadIdx.x) >> 5;
    unsigned int lane = threadIdx.x & 31u;
    float s = 0.0f;
    if (gw < 3 * BATCH) {
        unsigned int which = gw / BATCH;
        unsigned int b = gw % BATCH;
        const float* row;
        if (which == 0)      row = eu + (size_t)user[b]   * EMBED;
        else if (which == 1) row = ei + (size_t)item_i[b] * EMBED;
        else                 row = ei + (size_t)item_j[b] * EMBED;
        float2 v = reinterpret_cast<const float2*>(row)[lane];
        s = v.x * v.x + v.y * v.y;
    }
    #pragma unroll
    for (int o = 16; o; o >>= 1) s += __shfl_xor_sync(0xffffffffu, s, o);
    __shared__ float sh[8];
    unsigned int w = threadIdx.x >> 5;
    if (lane == 0) sh[w] = s;
    __syncthreads();
    if (threadIdx.x == 0) {
        float t = 0.0f;
        #pragma unroll
        for (int k = 0; k < 8; k++) t += sh[k];
        atomicAdd(out + 2 * BATCH, t * (0.5f / (float)BATCH));
    }
}

extern "C" void kernel_launch(void* const* d_in, const int* in_sizes, int n_in,
                              void* d_out, int out_size) {
    const int*   user   = (const int*)d_in[0];
    const int*   item_i = (const int*)d_in[1];
    const int*   item_j = (const int*)d_in[2];
    const int*   esrc   = (const int*)d_in[5];
    const int*   edst   = (const int*)d_in[6];
    const float* evals  = (const float*)d_in[7];
    const float* eu     = (const float*)d_in[8];
    const float* ei     = (const float*)d_in[9];
    float* out = (float*)d_out;

    const int gb = (int)((N4 + 255) / 256);          // table-wide float4 kernels
    const int eb = (NNZ + 255) / 256;                // per-edge kernels
    const int wb = (NTOT * 32 + 255) / 256;          // warp-per-node gather

    k_init<<<gb, 256>>>(eu, ei, out);

    // Build CSR (by src) fresh each launch.
    k_hist<<<eb, 256>>>(esrc);
    k_scan<<<1, SCAN_T>>>();
    k_reorder<<<eb, 256>>>(esrc, edst, evals);

    // 3 propagation layers, ping-pong A<->B, S accumulated in-kernel.
    k_gather<<<wb, 256>>>(0, 0);   // A -> B, S += B
    k_gather<<<wb, 256>>>(1, 0);   // B -> A, S += A
    k_gather<<<wb, 256>>>(0, 1);   // A -> (S only)

    k_pred<<<(BATCH * 32) / 256, 256>>>(user, item_i, item_j, out);
    k_reg<<<(3 * BATCH * 32) / 256, 256>>>(user, item_i, item_j, eu, ei, out);
}

// round 7
// speedup vs baseline: 1.6689x; 1.6689x over previous
#include <cuda_runtime.h>

#define N_USERS 100000
#define M_ITEMS 50000
#define NTOT    150000
#define EMBED   64
#define BATCH   8192
#define NNZ     2400000
#define TILE    1024                       // elements per scan tile
#define SBLK    ((NTOT + TILE - 1) / TILE) // 147 scan blocks

// Static device scratch (no allocation allowed).
__device__ float g_A[(size_t)NTOT * EMBED];   // ping
__device__ float g_B[(size_t)NTOT * EMBED];   // pong
__device__ float g_S[(size_t)NTOT * EMBED];   // running sum
__device__ int   g_cnt[NTOT + 1];
__device__ int   g_rs[NTOT + 1];              // CSR row starts
__device__ int   g_cur[NTOT];                 // scatter cursors
__device__ int   g_part[SBLK + 1];            // per-tile partial sums
__device__ int2  g_edge[NNZ];                 // packed (dst, val-bits), grouped by src

__device__ __forceinline__ float* pickAB(int sel) { return sel ? g_B : g_A; }

static const size_t N4 = (size_t)NTOT * EMBED / 4;

// A = S = concat(embed_user_0, embed_item_0); zero g_cnt and the reg_loss slot.
__global__ void k_init(const float* __restrict__ eu, const float* __restrict__ ei,
                       float* __restrict__ out) {
    size_t i = (size_t)blockIdx.x * blockDim.x + threadIdx.x;
    const size_t total = (size_t)NTOT * EMBED / 4;
    if (i >= total) return;
    const size_t userQ = (size_t)N_USERS * EMBED / 4;
    float4 v;
    if (i < userQ) v = reinterpret_cast<const float4*>(eu)[i];
    else           v = reinterpret_cast<const float4*>(ei)[i - userQ];
    reinterpret_cast<float4*>(g_A)[i] = v;
    reinterpret_cast<float4*>(g_S)[i] = v;
    if (i <= NTOT) g_cnt[i] = 0;
    if (i == 0) out[2 * BATCH] = 0.0f;
}

// Histogram edge sources.
__global__ void k_hist(const int* __restrict__ src) {
    unsigned int i = blockIdx.x * blockDim.x + threadIdx.x;
    if (i < NNZ) atomicAdd(&g_cnt[src[i]], 1);
}

// ---- Parallel exclusive scan of g_cnt[0..NTOT) -> g_rs, g_cur ----
// (A) per-tile reduce: block b sums g_cnt[b*TILE .. b*TILE+TILE) -> g_part[b]
__global__ void k_scanA() {
    int b = blockIdx.x;
    int t = threadIdx.x;                 // 256 threads, 4 elems each
    int base = b * TILE + t * 4;
    int s = 0;
    #pragma unroll
    for (int j = 0; j < 4; j++) {
        int idx = base + j;
        if (idx < NTOT) s += g_cnt[idx];
    }
    #pragma unroll
    for (int o = 16; o; o >>= 1) s += __shfl_xor_sync(0xffffffffu, s, o);
    __shared__ int sh[8];
    if ((t & 31) == 0) sh[t >> 5] = s;
    __syncthreads();
    if (t == 0) {
        int tot = 0;
        #pragma unroll
        for (int k = 0; k < 8; k++) tot += sh[k];
        g_part[b] = tot;
    }
}

// (B) one small block: exclusive scan of the SBLK partials (in place).
__global__ void k_scanB() {
    __shared__ int sp[256];
    int t = threadIdx.x;
    sp[t] = (t < SBLK) ? g_part[t] : 0;
    __syncthreads();
    #pragma unroll
    for (int o = 1; o < 256; o <<= 1) {
        int v = (t >= o) ? sp[t - o] : 0;
        __syncthreads();
        sp[t] += v;
        __syncthreads();
    }
    if (t < SBLK) g_part[t] = (t == 0) ? 0 : sp[t - 1];   // exclusive
    if (t == 0) g_rs[NTOT] = NNZ;                          // total is known
}

// (C) per-tile exclusive scan + block offset -> g_rs, g_cur.
__global__ void k_scanC() {
    __shared__ int sh[256];
    int b = blockIdx.x;
    int t = threadIdx.x;
    int base = b * TILE + t * 4;
    int c[4];
    int s = 0;
    #pragma unroll
    for (int j = 0; j < 4; j++) {
        int idx = base + j;
        c[j] = (idx < NTOT) ? g_cnt[idx] : 0;
        s += c[j];
    }
    sh[t] = s;
    __syncthreads();
    #pragma unroll
    for (int o = 1; o < 256; o <<= 1) {
        int v = (t >= o) ? sh[t - o] : 0;
        __syncthreads();
        sh[t] += v;
        __syncthreads();
    }
    int run = g_part[b] + ((t == 0) ? 0 : sh[t - 1]);      // exclusive within tile + tile offset
    #pragma unroll
    for (int j = 0; j < 4; j++) {
        int idx = base + j;
        if (idx < NTOT) { g_rs[idx] = run; g_cur[idx] = run; }
        run += c[j];
    }
}

// Bucket edges by src into packed (dst, val) records.
__global__ void k_reorder(const int* __restrict__ src, const int* __restrict__ dst,
                          const float* __restrict__ vals) {
    unsigned int i = blockIdx.x * blockDim.x + threadIdx.x;
    if (i >= NNZ) return;
    int s = src[i];
    int pos = atomicAdd(&g_cur[s], 1);
    g_edge[pos] = make_int2(dst[i], __float_as_int(vals[i]));
}

// One warp per node, MLP-8 pipelined gather; fused S += result.
__global__ void k_gather(int inSel, int last) {
    unsigned int gw = (blockIdx.x * blockDim.x + threadIdx.x) >> 5;
    if (gw >= NTOT) return;
    unsigned int lane = threadIdx.x & 31u;
    const float2* __restrict__ in = reinterpret_cast<const float2*>(pickAB(inSel));
    int beg = g_rs[gw];
    int end = g_rs[gw + 1];
    float ax = 0.0f, ay = 0.0f;
    for (int base = beg; base < end; base += 32) {
        int n = end - base; if (n > 32) n = 32;
        int2 ed = make_int2(0, 0);                       // pad: row 0, weight 0
        if (base + (int)lane < end) ed = __ldg(&g_edge[base + lane]);
        for (int k = 0; k < n; k += 8) {
            float2 x[8];
            float  v[8];
            #pragma unroll
            for (int j = 0; j < 8; j++) {
                int idx = k + j;
                int d  = __shfl_sync(0xffffffffu, ed.x, idx & 31);
                int vb = __shfl_sync(0xffffffffu, ed.y, idx & 31);
                v[j] = (idx < n) ? __int_as_float(vb) : 0.0f;
                x[j] = in[(size_t)d * (EMBED / 2) + lane];
            }
            #pragma unroll
            for (int j = 0; j < 8; j++) {
                ax = fmaf(v[j], x[j].x, ax);
                ay = fmaf(v[j], x[j].y, ay);
            }
        }
    }
    size_t idx = (size_t)gw * (EMBED / 2) + lane;
    if (!last) reinterpret_cast<float2*>(pickAB(inSel ^ 1))[idx] = make_float2(ax, ay);
    float2 s = reinterpret_cast<float2*>(g_S)[idx];
    reinterpret_cast<float2*>(g_S)[idx] = make_float2(s.x + ax, s.y + ay);
}

// Predictions: light_out = S/4; pred = dot(light_out[u], light_out[item]).
__global__ void k_pred(const int* __restrict__ user, const int* __restrict__ item_i,
                       const int* __restrict__ item_j, float* __restrict__ out) {
    unsigned int gw = (blockIdx.x * blockDim.x + threadIdx.x) >> 5;
    unsigned int lane = threadIdx.x & 31u;
    if (gw >= BATCH) return;
    int u  = user[gw];
    int ii = item_i[gw] + N_USERS;
    int jj = item_j[gw] + N_USERS;
    float2 ue = reinterpret_cast<const float2*>(g_S + (size_t)u  * EMBED)[lane];
    float2 ie = reinterpret_cast<const float2*>(g_S + (size_t)ii * EMBED)[lane];
    float2 je = reinterpret_cast<const float2*>(g_S + (size_t)jj * EMBED)[lane];
    float di = ue.x * ie.x + ue.y * ie.y;
    float dj = ue.x * je.x + ue.y * je.y;
    #pragma unroll
    for (int o = 16; o; o >>= 1) {
        di += __shfl_xor_sync(0xffffffffu, di, o);
        dj += __shfl_xor_sync(0xffffffffu, dj, o);
    }
    if (lane == 0) {
        out[gw]         = di * 0.0625f;   // (1/4)*(1/4)
        out[BATCH + gw] = dj * 0.0625f;
    }
}

// reg_loss = 0.5 * (sum u0^2 + sum i0^2 + sum j0^2) / BATCH
__global__ void k_reg(const int* __restrict__ user, const int* __restrict__ item_i,
                      const int* __restrict__ item_j,
                      const float* __restrict__ eu, const float* __restrict__ ei,
                      float* __restrict__ out) {
    unsigned int gw = (blockIdx.x * blockDim.x + threadIdx.x) >> 5;
    unsigned int lane = threadIdx.x & 31u;
    float s = 0.0f;
    if (gw < 3 * BATCH) {
        unsigned int which = gw / BATCH;
        unsigned int b = gw % BATCH;
        const float* row;
        if (which == 0)      row = eu + (size_t)user[b]   * EMBED;
        else if (which == 1) row = ei + (size_t)item_i[b] * EMBED;
        else                 row = ei + (size_t)item_j[b] * EMBED;
        float2 v = reinterpret_cast<const float2*>(row)[lane];
        s = v.x * v.x + v.y * v.y;
    }
    #pragma unroll
    for (int o = 16; o; o >>= 1) s += __shfl_xor_sync(0xffffffffu, s, o);
    __shared__ float sh[8];
    unsigned int w = threadIdx.x >> 5;
    if (lane == 0) sh[w] = s;
    __syncthreads();
    if (threadIdx.x == 0) {
        float t = 0.0f;
        #pragma unroll
        for (int k = 0; k < 8; k++) t += sh[k];
        atomicAdd(out + 2 * BATCH, t * (0.5f / (float)BATCH));
    }
}

extern "C" void kernel_launch(void* const* d_in, const int* in_sizes, int n_in,
                              void* d_out, int out_size) {
    const int*   user   = (const int*)d_in[0];
    const int*   item_i = (const int*)d_in[1];
    const int*   item_j = (const int*)d_in[2];
    const int*   esrc   = (const int*)d_in[5];
    const int*   edst   = (const int*)d_in[6];
    const float* evals  = (const float*)d_in[7];
    const float* eu     = (const float*)d_in[8];
    const float* ei     = (const float*)d_in[9];
    float* out = (float*)d_out;

    const int gb = (int)((N4 + 255) / 256);          // table-wide float4 kernels
    const int eb = (NNZ + 255) / 256;                // per-edge kernels
    const int wb = (NTOT * 32 + 255) / 256;          // warp-per-node gather

    k_init<<<gb, 256>>>(eu, ei, out);

    // Build CSR (by src) fresh each launch — scan now chip-parallel.
    k_hist<<<eb, 256>>>(esrc);
    k_scanA<<<SBLK, 256>>>();
    k_scanB<<<1, 256>>>();
    k_scanC<<<SBLK, 256>>>();
    k_reorder<<<eb, 256>>>(esrc, edst, evals);

    // 3 propagation layers, ping-pong A<->B, S accumulated in-kernel.
    k_gather<<<wb, 256>>>(0, 0);   // A -> B, S += B
    k_gather<<<wb, 256>>>(1, 0);   // B -> A, S += A
    k_gather<<<wb, 256>>>(0, 1);   // A -> (S only)

    k_pred<<<(BATCH * 32) / 256, 256>>>(user, item_i, item_j, out);
    k_reg<<<(3 * BATCH * 32) / 256, 256>>>(user, item_i, item_j, eu, ei, out);
}

// round 9
// speedup vs baseline: 2.2194x; 1.3299x over previous
#include <cuda_runtime.h>

#define N_USERS 100000
#define M_ITEMS 50000
#define NTOT    150000
#define EMBED   64
#define BATCH   8192
#define NNZ     2400000
#define TILE    1024                       // elements per scan tile
#define SBLK    ((NTOT + TILE - 1) / TILE) // 147 scan blocks
#define NQ      (3 * BATCH)                // query rows (user, item_i, item_j)

// Static device scratch (no allocation allowed).
__device__ float g_A[(size_t)NTOT * EMBED];   // ping
__device__ float g_B[(size_t)NTOT * EMBED];   // pong
__device__ float g_Sq[(size_t)NQ * EMBED];    // per-query running light_out sum
__device__ int   g_cnt[NTOT + 1];
__device__ int   g_rs[NTOT + 1];              // CSR row starts
__device__ int   g_cur[NTOT];                 // scatter cursors
__device__ int   g_part[SBLK + 1];            // per-tile partial sums
__device__ int2  g_edge[NNZ];                 // packed (dst, val-bits), grouped by src

__device__ __forceinline__ float* pickAB(int sel) { return sel ? g_B : g_A; }

static const size_t N4 = (size_t)NTOT * EMBED / 4;

// Map query slot q (0..NQ) -> node id.
__device__ __forceinline__ int qnode(unsigned int q, const int* __restrict__ user,
                                     const int* __restrict__ item_i,
                                     const int* __restrict__ item_j) {
    unsigned int which = q / BATCH;
    unsigned int b = q % BATCH;
    if (which == 0) return user[b];
    if (which == 1) return item_i[b] + N_USERS;
    return item_j[b] + N_USERS;
}

// A = concat(embed_user_0, embed_item_0); zero g_cnt and the reg_loss slot.
__global__ void k_init(const float* __restrict__ eu, const float* __restrict__ ei,
                       float* __restrict__ out) {
    size_t i = (size_t)blockIdx.x * blockDim.x + threadIdx.x;
    const size_t total = (size_t)NTOT * EMBED / 4;
    if (i >= total) return;
    const size_t userQ = (size_t)N_USERS * EMBED / 4;
    float4 v;
    if (i < userQ) v = reinterpret_cast<const float4*>(eu)[i];
    else           v = reinterpret_cast<const float4*>(ei)[i - userQ];
    reinterpret_cast<float4*>(g_A)[i] = v;
    if (i <= NTOT) g_cnt[i] = 0;
    if (i == 0) out[2 * BATCH] = 0.0f;
}

// Histogram edge sources.
__global__ void k_hist(const int* __restrict__ src) {
    unsigned int i = blockIdx.x * blockDim.x + threadIdx.x;
    if (i < NNZ) atomicAdd(&g_cnt[src[i]], 1);
}

// ---- Parallel exclusive scan of g_cnt[0..NTOT) -> g_rs, g_cur ----
__global__ void k_scanA() {
    int b = blockIdx.x;
    int t = threadIdx.x;                 // 256 threads, 4 elems each
    int base = b * TILE + t * 4;
    int s = 0;
    #pragma unroll
    for (int j = 0; j < 4; j++) {
        int idx = base + j;
        if (idx < NTOT) s += g_cnt[idx];
    }
    #pragma unroll
    for (int o = 16; o; o >>= 1) s += __shfl_xor_sync(0xffffffffu, s, o);
    __shared__ int sh[8];
    if ((t & 31) == 0) sh[t >> 5] = s;
    __syncthreads();
    if (t == 0) {
        int tot = 0;
        #pragma unroll
        for (int k = 0; k < 8; k++) tot += sh[k];
        g_part[b] = tot;
    }
}

__global__ void k_scanB() {
    __shared__ int sp[256];
    int t = threadIdx.x;
    sp[t] = (t < SBLK) ? g_part[t] : 0;
    __syncthreads();
    #pragma unroll
    for (int o = 1; o < 256; o <<= 1) {
        int v = (t >= o) ? sp[t - o] : 0;
        __syncthreads();
        sp[t] += v;
        __syncthreads();
    }
    if (t < SBLK) g_part[t] = (t == 0) ? 0 : sp[t - 1];   // exclusive
    if (t == 0) g_rs[NTOT] = NNZ;
}

__global__ void k_scanC() {
    __shared__ int sh[256];
    int b = blockIdx.x;
    int t = threadIdx.x;
    int base = b * TILE + t * 4;
    int c[4];
    int s = 0;
    #pragma unroll
    for (int j = 0; j < 4; j++) {
        int idx = base + j;
        c[j] = (idx < NTOT) ? g_cnt[idx] : 0;
        s += c[j];
    }
    sh[t] = s;
    __syncthreads();
    #pragma unroll
    for (int o = 1; o < 256; o <<= 1) {
        int v = (t >= o) ? sh[t - o] : 0;
        __syncthreads();
        sh[t] += v;
        __syncthreads();
    }
    int run = g_part[b] + ((t == 0) ? 0 : sh[t - 1]);
    #pragma unroll
    for (int j = 0; j < 4; j++) {
        int idx = base + j;
        if (idx < NTOT) { g_rs[idx] = run; g_cur[idx] = run; }
        run += c[j];
    }
}

// Bucket edges by src into packed (dst, val) records.
__global__ void k_reorder(const int* __restrict__ src, const int* __restrict__ dst,
                          const float* __restrict__ vals) {
    unsigned int i = blockIdx.x * blockDim.x + threadIdx.x;
    if (i >= NNZ) return;
    int s = src[i];
    int pos = atomicAdd(&g_cur[s], 1);
    g_edge[pos] = make_int2(dst[i], __float_as_int(vals[i]));
}

// One warp per node, MLP-8 pipelined full-table gather (inSel -> inSel^1).
__global__ void k_gather(int inSel) {
    unsigned int gw = (blockIdx.x * blockDim.x + threadIdx.x) >> 5;
    if (gw >= NTOT) return;
    unsigned int lane = threadIdx.x & 31u;
    const float2* __restrict__ in = reinterpret_cast<const float2*>(pickAB(inSel));
    int beg = g_rs[gw];
    int end = g_rs[gw + 1];
    float ax = 0.0f, ay = 0.0f;
    for (int base = beg; base < end; base += 32) {
        int n = end - base; if (n > 32) n = 32;
        int2 ed = make_int2(0, 0);                       // pad: row 0, weight 0
        if (base + (int)lane < end) ed = __ldg(&g_edge[base + lane]);
        for (int k = 0; k < n; k += 8) {
            float2 x[8];
            float  v[8];
            #pragma unroll
            for (int j = 0; j < 8; j++) {
                int idx = k + j;
                int d  = __shfl_sync(0xffffffffu, ed.x, idx & 31);
                int vb = __shfl_sync(0xffffffffu, ed.y, idx & 31);
                v[j] = (idx < n) ? __int_as_float(vb) : 0.0f;
                x[j] = in[(size_t)d * (EMBED / 2) + lane];
            }
            #pragma unroll
            for (int j = 0; j < 8; j++) {
                ax = fmaf(v[j], x[j].x, ax);
                ay = fmaf(v[j], x[j].y, ay);
            }
        }
    }
    size_t idx = (size_t)gw * (EMBED / 2) + lane;
    reinterpret_cast<float2*>(pickAB(inSel ^ 1))[idx] = make_float2(ax, ay);
}

// S_q (set or +=) from a full table at the queried rows. add=0: store, 1: accumulate.
__global__ void k_qacc(const int* __restrict__ user, const int* __restrict__ item_i,
                       const int* __restrict__ item_j, int sel, int add) {
    unsigned int gw = (blockIdx.x * blockDim.x + threadIdx.x) >> 5;
    if (gw >= NQ) return;
    unsigned int lane = threadIdx.x & 31u;
    int node = qnode(gw, user, item_i, item_j);
    float2 v = reinterpret_cast<const float2*>(pickAB(sel))[(size_t)node * (EMBED / 2) + lane];
    float2* sq = reinterpret_cast<float2*>(g_Sq) + (size_t)gw * (EMBED / 2) + lane;
    if (add) {
        float2 s = *sq;
        v.x += s.x; v.y += s.y;
    }
    *sq = v;
}

// Layer 3 restricted to queried rows: S_q[q] += sum_{e in row(node_q)} val_e * in[dst_e].
__global__ void k_qgather(const int* __restrict__ user, const int* __restrict__ item_i,
                          const int* __restrict__ item_j, int inSel) {
    unsigned int gw = (blockIdx.x * blockDim.x + threadIdx.x) >> 5;
    if (gw >= NQ) return;
    unsigned int lane = threadIdx.x & 31u;
    const float2* __restrict__ in = reinterpret_cast<const float2*>(pickAB(inSel));
    int node = qnode(gw, user, item_i, item_j);
    int beg = g_rs[node];
    int end = g_rs[node + 1];
    float ax = 0.0f, ay = 0.0f;
    for (int base = beg; base < end; base += 32) {
        int n = end - base; if (n > 32) n = 32;
        int2 ed = make_int2(0, 0);
        if (base + (int)lane < end) ed = __ldg(&g_edge[base + lane]);
        for (int k = 0; k < n; k += 8) {
            float2 x[8];
            float  v[8];
            #pragma unroll
            for (int j = 0; j < 8; j++) {
                int idx = k + j;
                int d  = __shfl_sync(0xffffffffu, ed.x, idx & 31);
                int vb = __shfl_sync(0xffffffffu, ed.y, idx & 31);
                v[j] = (idx < n) ? __int_as_float(vb) : 0.0f;
                x[j] = in[(size_t)d * (EMBED / 2) + lane];
            }
            #pragma unroll
            for (int j = 0; j < 8; j++) {
                ax = fmaf(v[j], x[j].x, ax);
                ay = fmaf(v[j], x[j].y, ay);
            }
        }
    }
    float2* sq = reinterpret_cast<float2*>(g_Sq) + (size_t)gw * (EMBED / 2) + lane;
    float2 s = *sq;
    *sq = make_float2(s.x + ax, s.y + ay);
}

// Predictions from S_q: pred_i[b] = dot(Sq[b], Sq[BATCH+b]) / 16, same for j.
__global__ void k_pred(float* __restrict__ out) {
    unsigned int gw = (blockIdx.x * blockDim.x + threadIdx.x) >> 5;
    unsigned int lane = threadIdx.x & 31u;
    if (gw >= BATCH) return;
    const float2* sq = reinterpret_cast<const float2*>(g_Sq);
    float2 ue = sq[(size_t)gw * (EMBED / 2) + lane];
    float2 ie = sq[(size_t)(BATCH + gw) * (EMBED / 2) + lane];
    float2 je = sq[(size_t)(2 * BATCH + gw) * (EMBED / 2) + lane];
    float di = ue.x * ie.x + ue.y * ie.y;
    float dj = ue.x * je.x + ue.y * je.y;
    #pragma unroll
    for (int o = 16; o; o >>= 1) {
        di += __shfl_xor_sync(0xffffffffu, di, o);
        dj += __shfl_xor_sync(0xffffffffu, dj, o);
    }
    if (lane == 0) {
        out[gw]         = di * 0.0625f;   // (1/4)*(1/4)
        out[BATCH + gw] = dj * 0.0625f;
    }
}

// reg_loss = 0.5 * (sum u0^2 + sum i0^2 + sum j0^2) / BATCH
__global__ void k_reg(const int* __restrict__ user, const int* __restrict__ item_i,
                      const int* __restrict__ item_j,
                      const float* __restrict__ eu, const float* __restrict__ ei,
                      float* __restrict__ out) {
    unsigned int gw = (blockIdx.x * blockDim.x + threadIdx.x) >> 5;
    unsigned int lane = threadIdx.x & 31u;
    float s = 0.0f;
    if (gw < NQ) {
        unsigned int which = gw / BATCH;
        unsigned int b = gw % BATCH;
        const float* row;
        if (which == 0)      row = eu + (size_t)user[b]   * EMBED;
        else if (which == 1) row = ei + (size_t)item_i[b] * EMBED;
        else                 row = ei + (size_t)item_j[b] * EMBED;
        float2 v = reinterpret_cast<const float2*>(row)[lane];
        s = v.x * v.x + v.y * v.y;
    }
    #pragma unroll
    for (int o = 16; o; o >>= 1) s += __shfl_xor_sync(0xffffffffu, s, o);
    __shared__ float sh[8];
    unsigned int w = threadIdx.x >> 5;
    if (lane == 0) sh[w] = s;
    __syncthreads();
    if (threadIdx.x == 0) {
        float t = 0.0f;
        #pragma unroll
        for (int k = 0; k < 8; k++) t += sh[k];
        atomicAdd(out + 2 * BATCH, t * (0.5f / (float)BATCH));
    }
}

extern "C" void kernel_launch(void* const* d_in, const int* in_sizes, int n_in,
                              void* d_out, int out_size) {
    const int*   user   = (const int*)d_in[0];
    const int*   item_i = (const int*)d_in[1];
    const int*   item_j = (const int*)d_in[2];
    const int*   esrc   = (const int*)d_in[5];
    const int*   edst   = (const int*)d_in[6];
    const float* evals  = (const float*)d_in[7];
    const float* eu     = (const float*)d_in[8];
    const float* ei     = (const float*)d_in[9];
    float* out = (float*)d_out;

    const int gb = (int)((N4 + 255) / 256);          // table-wide float4 kernels
    const int eb = (NNZ + 255) / 256;                // per-edge kernels
    const int wb = (NTOT * 32 + 255) / 256;          // warp-per-node gather
    const int qb = (NQ * 32 + 255) / 256;            // warp-per-query kernels

    k_init<<<gb, 256>>>(eu, ei, out);

    // Build CSR (by src) fresh each launch.
    k_hist<<<eb, 256>>>(esrc);
    k_scanA<<<SBLK, 256>>>();
    k_scanB<<<1, 256>>>();
    k_scanC<<<SBLK, 256>>>();
    k_reorder<<<eb, 256>>>(esrc, edst, evals);

    // S_q = A0 at queried rows.
    k_qacc<<<qb, 256>>>(user, item_i, item_j, 0, 0);

    // Layer 1: A -> B ; S_q += B at queried rows.
    k_gather<<<wb, 256>>>(0);
    k_qacc<<<qb, 256>>>(user, item_i, item_j, 1, 1);

    // Layer 2: B -> A ; S_q += A at queried rows.
    k_gather<<<wb, 256>>>(1);
    k_qacc<<<qb, 256>>>(user, item_i, item_j, 0, 1);

    // Layer 3 only at queried rows: S_q += gather(A).
    k_qgather<<<qb, 256>>>(user, item_i, item_j, 0);

    k_pred<<<(BATCH * 32) / 256, 256>>>(out);
    k_reg<<<qb, 256>>>(user, item_i, item_j, eu, ei, out);
}